// round 9
// baseline (speedup 1.0000x reference)
#include <cuda_runtime.h>
#include <math.h>
#include <stdint.h>

// Problem constants
#define T_ALL 16
#define B_    32
#define C_    256
#define HW    256
#define KLAG  4
#define TQ    12
#define CHW   (C_ * HW)          // 65536
#define BCHW  (B_ * CHW)         // 2097152
#define NPAIR (TQ * B_)          // 384

// Output layout (float32)
#define SPK_N    (T_ALL * BCHW)
#define OUT_LOSS (SPK_N)
#define OUT_LSP  (SPK_N + 1)
#define OUT_LSN  (SPK_N + 1 + NPAIR)

// Byte matrices (values 0/1), natural layout:
//   g_ctx8[t][b][c][hw]  (t = 0..11)       g_s8[t-4][b][c][hw]  (t = 4..15)
__device__ unsigned char g_ctx8[(size_t)TQ * BCHW];
__device__ unsigned char g_s8[(size_t)TQ * BCHW];
__device__ float g_ppos[NPAIR * 4];   // [pair][ot*2+ct]
__device__ float g_pneg[NPAIR * 4];

// ---------------------------------------------------------------------------
// 1) Fused copy + LIF scan + byte emit (4 hw elems / thread, all coalesced).
// ---------------------------------------------------------------------------
__global__ __launch_bounds__(256)
void scan_kernel(const float4* __restrict__ spk, float4* __restrict__ out) {
    const int i = blockIdx.x * 256 + threadIdx.x;        // 0 .. BCHW/4-1
    unsigned* ctx8w = (unsigned*)g_ctx8;
    unsigned* s8w   = (unsigned*)g_s8;

    float m0 = 0.f, m1 = 0.f, m2 = 0.f, m3 = 0.f;
#pragma unroll
    for (int t = 0; t < T_ALL; t++) {
        float4 v = spk[t * (BCHW / 4) + i];
        out[t * (BCHW / 4) + i] = v;
        float r0 = (m0 > 1.f) ? 1.f : 0.f;
        float r1 = (m1 > 1.f) ? 1.f : 0.f;
        float r2 = (m2 > 1.f) ? 1.f : 0.f;
        float r3 = (m3 > 1.f) ? 1.f : 0.f;
        m0 = 0.5f * m0 + v.x - r0;
        m1 = 0.5f * m1 + v.y - r1;
        m2 = 0.5f * m2 + v.z - r2;
        m3 = 0.5f * m3 + v.w - r3;
        if (t >= KLAG) {
            unsigned sv = (v.x > 0.5f ? 1u : 0u)        | (v.y > 0.5f ? 1u : 0u) << 8
                        | (v.z > 0.5f ? 1u : 0u) << 16  | (v.w > 0.5f ? 1u : 0u) << 24;
            s8w[(t - KLAG) * (BCHW / 4) + i] = sv;
        }
        if (t < TQ) {
            unsigned cv = (m0 > 1.f ? 1u : 0u)        | (m1 > 1.f ? 1u : 0u) << 8
                        | (m2 > 1.f ? 1u : 0u) << 16  | (m3 > 1.f ? 1u : 0u) << 24;
            ctx8w[t * (BCHW / 4) + i] = cv;
        }
    }
}

// ---------------------------------------------------------------------------
// 2) INT8 GEMM  M = ctx(128 x 256hw) @ S^T(256hw x 128)  + fp32 W-dot epilogue.
//    CTA = (pair, pos/neg, otile, ctile): exact s32 accumulation.
// ---------------------------------------------------------------------------
#define PITCH     80                    // 64 data + 16 pad bytes per smem row
#define STG       (128 * PITCH)        // 10240 B per stage per operand
#define OFF_B0    (4 * STG)            // 40960
#define OFF_RED   (8 * STG)            // 81920
#define SMEM_TOTAL (OFF_RED + 64)

__device__ __forceinline__ uint32_t smem_u32(const void* p) {
    uint32_t a;
    asm("{ .reg .u64 t; cvta.to.shared.u64 t, %1; cvt.u32.u64 %0, t; }" : "=r"(a) : "l"(p));
    return a;
}
__device__ __forceinline__ void cp16(uint32_t dst, const void* src) {
    asm volatile("cp.async.cg.shared.global [%0], [%1], 16;"
                 :: "r"(dst), "l"(src) : "memory");
}
__device__ __forceinline__ void ldsm4(uint32_t addr, uint32_t& r0, uint32_t& r1,
                                      uint32_t& r2, uint32_t& r3) {
    asm volatile("ldmatrix.sync.aligned.m8n8.x4.shared.b16 {%0,%1,%2,%3}, [%4];"
                 : "=r"(r0), "=r"(r1), "=r"(r2), "=r"(r3) : "r"(addr));
}
__device__ __forceinline__ void mma_s8(int* c, const uint32_t* a, const uint32_t* b) {
    asm volatile(
        "mma.sync.aligned.m16n8k32.row.col.s32.s8.s8.s32 "
        "{%0,%1,%2,%3}, {%4,%5,%6,%7}, {%8,%9}, {%0,%1,%2,%3};"
        : "+r"(c[0]), "+r"(c[1]), "+r"(c[2]), "+r"(c[3])
        : "r"(a[0]), "r"(a[1]), "r"(a[2]), "r"(a[3]), "r"(b[0]), "r"(b[1]));
}

__global__ __launch_bounds__(256, 2)
void mma_kernel(const float* __restrict__ Wg, const int* __restrict__ ridx) {
    extern __shared__ char smem[];
    const uint32_t sb = smem_u32(smem);
    const int tid = threadIdx.x, wid = tid >> 5, lane = tid & 31;

    int bi = blockIdx.x;
    const int ct = bi & 1;  bi >>= 1;
    const int ot = bi & 1;  bi >>= 1;
    const int pn = bi & 1;  bi >>= 1;
    const int pair = bi;                       // 0..383
    const int tq = pair >> 5, b = pair & 31;
    const int bsel = pn ? __ldg(&ridx[b]) : b; // neg uses spk[t+4, ridx[b]]

    const unsigned char* Asrc =
        g_ctx8 + (size_t)tq * BCHW + (size_t)(b * C_ + ot * 128) * 256;
    const unsigned char* Bsrc =
        g_s8   + (size_t)tq * BCHW + (size_t)(bsel * C_ + ct * 128) * 256;

    // Issue all 4 K-stages up front (kt = 64 hw-bytes per stage).
#pragma unroll
    for (int s = 0; s < 4; s++) {
#pragma unroll
        for (int q = 0; q < 4; q++) {
            int idx = q * 256 + tid;           // 0..1023
            int row2 = idx >> 2, chunk = idx & 3;
            if (row2 < 128) {
                cp16(sb + s * STG + row2 * PITCH + chunk * 16,
                     Asrc + (size_t)row2 * 256 + s * 64 + chunk * 16);
            } else {
                int r = row2 - 128;
                cp16(sb + OFF_B0 + s * STG + r * PITCH + chunk * 16,
                     Bsrc + (size_t)r * 256 + s * 64 + chunk * 16);
            }
        }
        asm volatile("cp.async.commit_group;" ::: "memory");
    }

    const int warpM = wid >> 2, warpN = wid & 3;  // 2 x 4 over 128m x 128n
    int acc[4][4][4];
#pragma unroll
    for (int mi = 0; mi < 4; mi++)
#pragma unroll
        for (int ni = 0; ni < 4; ni++)
#pragma unroll
            for (int e = 0; e < 4; e++) acc[mi][ni][e] = 0;

#pragma unroll
    for (int s = 0; s < 4; s++) {
        if (s == 0)      asm volatile("cp.async.wait_group 3;" ::: "memory");
        else if (s == 1) asm volatile("cp.async.wait_group 2;" ::: "memory");
        else if (s == 2) asm volatile("cp.async.wait_group 1;" ::: "memory");
        else             asm volatile("cp.async.wait_group 0;" ::: "memory");
        __syncthreads();

        const uint32_t aStg = sb + s * STG;
        const uint32_t bStg = sb + OFF_B0 + s * STG;
#pragma unroll
        for (int kc = 0; kc < 2; kc++) {
            uint32_t a[4][4], bfr[4][2];
#pragma unroll
            for (int mi = 0; mi < 4; mi++) {
                uint32_t addr = aStg
                    + (warpM * 64 + mi * 16 + (lane & 15)) * PITCH
                    + kc * 32 + (lane >> 4) * 16;
                ldsm4(addr, a[mi][0], a[mi][1], a[mi][2], a[mi][3]);
            }
#pragma unroll
            for (int h = 0; h < 2; h++) {
                uint32_t addr = bStg
                    + (warpN * 32 + h * 16 + (lane >> 4) * 8 + (lane & 7)) * PITCH
                    + kc * 32 + ((lane >> 3) & 1) * 16;
                uint32_t r0, r1, r2, r3;
                ldsm4(addr, r0, r1, r2, r3);
                bfr[2 * h + 0][0] = r0; bfr[2 * h + 0][1] = r1;
                bfr[2 * h + 1][0] = r2; bfr[2 * h + 1][1] = r3;
            }
#pragma unroll
            for (int mi = 0; mi < 4; mi++)
#pragma unroll
                for (int ni = 0; ni < 4; ni++)
                    mma_s8(acc[mi][ni], a[mi], bfr[ni]);
        }
    }

    // Epilogue: fp32 dot with W over the exact integer M tile.
    float sum = 0.f;
#pragma unroll
    for (int mi = 0; mi < 4; mi++) {
        int o0 = ot * 128 + warpM * 64 + mi * 16 + (lane >> 2);
#pragma unroll
        for (int ni = 0; ni < 4; ni++) {
            int c0 = ct * 128 + warpN * 32 + ni * 8 + (lane & 3) * 2;
            float2 w0 = __ldg((const float2*)&Wg[o0 * C_ + c0]);
            float2 w1 = __ldg((const float2*)&Wg[(o0 + 8) * C_ + c0]);
            int* a = acc[mi][ni];
            sum += w0.x * (float)a[0] + w0.y * (float)a[1]
                 + w1.x * (float)a[2] + w1.y * (float)a[3];
        }
    }

#pragma unroll
    for (int off = 16; off > 0; off >>= 1)
        sum += __shfl_down_sync(0xFFFFFFFFu, sum, off);
    float* red = (float*)(smem + OFF_RED);
    if (lane == 0) red[wid] = sum;
    __syncthreads();
    if (tid == 0) {
        float t = 0.f;
#pragma unroll
        for (int w = 0; w < 8; w++) t += red[w];
        if (pn == 0) g_ppos[pair * 4 + ot * 2 + ct] = t;
        else         g_pneg[pair * 4 + ot * 2 + ct] = t;
    }
}

// ---------------------------------------------------------------------------
// 3) Finalize
// ---------------------------------------------------------------------------
__global__ void finalize_kernel(float* __restrict__ out) {
    __shared__ float s_neg[TQ][B_];
    __shared__ float s_lsp[NPAIR];
    __shared__ float s_lsn[TQ];
    int tid = threadIdx.x;
    int tq = tid >> 5, b = tid & 31;

    float sp = 0.f, sn = 0.f;
#pragma unroll
    for (int s = 0; s < 4; s++) {
        sp += g_ppos[tid * 4 + s];
        sn += g_pneg[tid * 4 + s];
    }
    float score_pos = expf(sp * (1.0f / (float)CHW)) + 1e-4f;
    float score_neg = expf(sn * (1.0f / (float)CHW)) + 1e-4f;
    float lsp = logf(score_pos);
    s_neg[tq][b] = score_neg;
    s_lsp[tid]   = lsp;
    out[OUT_LSP + tid] = lsp;
    __syncthreads();
    if (b == 0) {
        float s = 0.0f;
#pragma unroll
        for (int bb = 0; bb < B_; bb++) s += s_neg[tq][bb];
        float lsn = logf(s);
        s_lsn[tq] = lsn;
        out[OUT_LSN + tq] = lsn;
    }
    __syncthreads();
    if (tid == 0) {
        float a = 0.0f;
        for (int i = 0; i < NPAIR; i++) a += (-s_lsp[i] + s_lsn[i >> 5]);
        out[OUT_LOSS] = a * (1.0f / (float)NPAIR);
    }
}

// ---------------------------------------------------------------------------
extern "C" void kernel_launch(void* const* d_in, const int* in_sizes, int n_in,
                              void* d_out, int out_size) {
    const float* spk  = (const float*)d_in[0];
    const float* Wg   = (const float*)d_in[2];
    const int*   ridx = (const int*)d_in[3];
    float* out = (float*)d_out;

    static int configured = 0;
    if (!configured) {
        cudaFuncSetAttribute(mma_kernel, cudaFuncAttributeMaxDynamicSharedMemorySize,
                             SMEM_TOTAL);
        configured = 1;
    }

    scan_kernel<<<BCHW / 4 / 256, 256>>>((const float4*)spk, (float4*)out);
    mma_kernel<<<NPAIR * 8, 256, SMEM_TOTAL>>>(Wg, ridx);   // pair x pn x ot x ct
    finalize_kernel<<<1, NPAIR>>>(out);
}

// round 11
// speedup vs baseline: 1.9816x; 1.9816x over previous
#include <cuda_runtime.h>
#include <cuda_fp16.h>
#include <math.h>
#include <stdint.h>

// Problem constants
#define T_ALL 16
#define B_    32
#define C_    256
#define HW    256
#define KLAG  4
#define TQ    12
#define CHW   (C_ * HW)          // 65536
#define BCHW  (B_ * CHW)         // 2097152
#define NPAIR (TQ * B_)          // 384

// Output layout (float32)
#define SPK_N    (T_ALL * BCHW)
#define OUT_LOSS (SPK_N)
#define OUT_LSP  (SPK_N + 1)
#define OUT_LSN  (SPK_N + 1 + NPAIR)

// Bit planes: [t][b][c][8 words]; consistent packed-hw permutation everywhere.
#define NWORDS (TQ * BCHW / 32)
__device__ unsigned g_ctxb[NWORDS];
__device__ unsigned g_spkb[NWORDS];
__device__ __half   g_w16[C_ * C_];      // fp16 copy of W
__device__ float    g_ppos[NPAIR * 8];   // [pair][oh*4+nh*2+kh]
__device__ float    g_pneg[NPAIR * 8];

// ---------------------------------------------------------------------------
// 1) Fused copy + LIF scan + bitpack; blocks 0..63 also convert W -> fp16.
// ---------------------------------------------------------------------------
__global__ __launch_bounds__(256)
void scan_kernel(const float4* __restrict__ spk, float4* __restrict__ out,
                 const float4* __restrict__ Wg) {
    const int i    = blockIdx.x * 256 + threadIdx.x;   // 0 .. BCHW/4-1
    const int lane = threadIdx.x & 31;
    const int row   = i >> 6;
    const int wbase = row * 8 + ((i & 63) >> 5) * 4;

    float m0 = 0.f, m1 = 0.f, m2 = 0.f, m3 = 0.f;
#pragma unroll
    for (int t = 0; t < T_ALL; t++) {
        float4 v = spk[t * (BCHW / 4) + i];
        out[t * (BCHW / 4) + i] = v;
        float r0 = (m0 > 1.f) ? 1.f : 0.f;
        float r1 = (m1 > 1.f) ? 1.f : 0.f;
        float r2 = (m2 > 1.f) ? 1.f : 0.f;
        float r3 = (m3 > 1.f) ? 1.f : 0.f;
        m0 = 0.5f * m0 + v.x - r0;
        m1 = 0.5f * m1 + v.y - r1;
        m2 = 0.5f * m2 + v.z - r2;
        m3 = 0.5f * m3 + v.w - r3;
        if (t >= KLAG) {
            unsigned b0 = __ballot_sync(0xFFFFFFFFu, v.x > 0.5f);
            unsigned b1 = __ballot_sync(0xFFFFFFFFu, v.y > 0.5f);
            unsigned b2 = __ballot_sync(0xFFFFFFFFu, v.z > 0.5f);
            unsigned b3 = __ballot_sync(0xFFFFFFFFu, v.w > 0.5f);
            if (lane == 0) {
                unsigned* p = &g_spkb[(t - KLAG) * (BCHW / 32) + wbase];
                p[0] = b0; p[1] = b1; p[2] = b2; p[3] = b3;
            }
        }
        if (t < TQ) {
            unsigned c0 = __ballot_sync(0xFFFFFFFFu, m0 > 1.f);
            unsigned c1 = __ballot_sync(0xFFFFFFFFu, m1 > 1.f);
            unsigned c2 = __ballot_sync(0xFFFFFFFFu, m2 > 1.f);
            unsigned c3 = __ballot_sync(0xFFFFFFFFu, m3 > 1.f);
            if (lane == 0) {
                unsigned* p = &g_ctxb[t * (BCHW / 32) + wbase];
                p[0] = c0; p[1] = c1; p[2] = c2; p[3] = c3;
            }
        }
    }
    // W -> fp16 (65536 elems = 16384 float4, blocks 0..63)
    if (blockIdx.x < 64) {
        int idx = blockIdx.x * 256 + threadIdx.x;      // 0..16383
        float4 w = Wg[idx];
        __half2 lo = __floats2half2_rn(w.x, w.y);
        __half2 hi = __floats2half2_rn(w.z, w.w);
        *(uint2*)&g_w16[idx * 4] =
            make_uint2(*(uint32_t*)&lo, *(uint32_t*)&hi);
    }
}

// ---------------------------------------------------------------------------
// 2) fp16 mma.sync GEMM + masked-add epilogue, occupancy-2 tiles.
//    CTA = (pair, oh, nh, kh): X_tile[128m x 128n] partial over k in kh half.
// ---------------------------------------------------------------------------
#define PITCH 272                       // 128 fp16 (256 B) + 16 B pad
#define OFF_BNEG  0
#define OFF_RED   16                    // 16 floats
#define OFF_STAGE 128                   // 1024 u32 = 4096 B
#define OFF_MASKP 4224                  // 512 u32
#define OFF_MASKN 6272                  // 512 u32
#define OFF_A     8320                  // 128 x 272 = 34816
#define OFF_B     43136                 // 128 x 272 = 34816
#define SMEM_TOTAL 77952

__device__ __forceinline__ uint32_t smem_u32(const void* p) {
    uint32_t a;
    asm("{ .reg .u64 t; cvta.to.shared.u64 t, %1; cvt.u32.u64 %0, t; }" : "=r"(a) : "l"(p));
    return a;
}
__device__ __forceinline__ void cp16(uint32_t dst, const void* src) {
    asm volatile("cp.async.cg.shared.global [%0], [%1], 16;"
                 :: "r"(dst), "l"(src) : "memory");
}
__device__ __forceinline__ void ldsm4(uint32_t addr, uint32_t& r0, uint32_t& r1,
                                      uint32_t& r2, uint32_t& r3) {
    asm volatile("ldmatrix.sync.aligned.m8n8.x4.shared.b16 {%0,%1,%2,%3}, [%4];"
                 : "=r"(r0), "=r"(r1), "=r"(r2), "=r"(r3) : "r"(addr));
}
__device__ __forceinline__ void mma_f16(float* c, const uint32_t* a, const uint32_t* b) {
    asm volatile(
        "mma.sync.aligned.m16n8k16.row.col.f32.f16.f16.f32 "
        "{%0,%1,%2,%3}, {%4,%5,%6,%7}, {%8,%9}, {%0,%1,%2,%3};"
        : "+f"(c[0]), "+f"(c[1]), "+f"(c[2]), "+f"(c[3])
        : "r"(a[0]), "r"(a[1]), "r"(a[2]), "r"(a[3]), "r"(b[0]), "r"(b[1]));
}

__global__ __launch_bounds__(256, 2)
void mma_kernel(const int* __restrict__ ridx) {
    extern __shared__ char smem[];
    const uint32_t sb = smem_u32(smem);
    unsigned* stage = (unsigned*)(smem + OFF_STAGE);
    unsigned* maskP = (unsigned*)(smem + OFF_MASKP);
    unsigned* maskN = (unsigned*)(smem + OFF_MASKN);
    float*    red   = (float*)(smem + OFF_RED);

    const int tid = threadIdx.x, wid = tid >> 5, lane = tid & 31;
    int bi = blockIdx.x;
    const int kh = bi & 1;  bi >>= 1;
    const int nh = bi & 1;  bi >>= 1;
    const int oh = bi & 1;  bi >>= 1;
    const int pair = bi;                      // 0..383
    const int tq = pair >> 5, bs = pair & 31;

    // inverse permutation
    if (tid < 32 && ridx[tid] == bs) *(int*)(smem + OFF_BNEG) = tid;
    __syncthreads();
    const int bneg = *(const int*)(smem + OFF_BNEG);

    // Stage spk bit words for this kh half (1024 words)
    {
        const uint4* src = (const uint4*)
            (g_spkb + ((size_t)(tq * B_ + bs) * C_ + kh * 128) * 8);
        ((uint4*)stage)[tid & 255] = src[tid];   // 256 uint4, tid 0..255
    }
    // Masks: rows o in oh-half, words wi in nh-half (4 per row)
    {
        if (tid < 128) {
            const uint4* mp = (const uint4*)
                (g_ctxb + ((size_t)(tq * B_ + bs) * C_ + oh * 128 + tid) * 8 + nh * 4);
            ((uint4*)maskP)[tid] = mp[0];
        } else {
            int r = tid - 128;
            const uint4* mn = (const uint4*)
                (g_ctxb + ((size_t)(tq * B_ + bneg) * C_ + oh * 128 + r) * 8 + nh * 4);
            ((uint4*)maskN)[r] = mn[0];
        }
    }
    // A tile via cp.async: W[oh*128 + m][kh*128 + k] fp16, 16B chunks
    {
#pragma unroll
        for (int q = 0; q < 8; q++) {
            int idx = q * 256 + tid;            // 0..2047
            int r = idx >> 4, ch = idx & 15;
            cp16(sb + OFF_A + r * PITCH + ch * 16,
                 (const char*)g_w16 + ((size_t)(oh * 128 + r) * C_ + kh * 128) * 2 + ch * 16);
        }
        asm volatile("cp.async.commit_group;" ::: "memory");
    }
    __syncthreads();   // stage visible

    // Expand B tile: row n (packed hw, nh half), cols k (c local, kh half).
    {
        const int rloc = tid >> 1;              // 0..127
        const int half = tid & 1;               // k-half of the row
        const int w    = nh * 4 + (rloc >> 5);  // ctx/spk word index
        const int bit  = rloc & 31;
        char* brow = smem + OFF_B + rloc * PITCH + half * 128;
#pragma unroll
        for (int c8 = 0; c8 < 8; c8++) {
            int cb = half * 64 + c8 * 8;
            uint32_t h[4];
#pragma unroll
            for (int j = 0; j < 4; j++) {
                unsigned b0 = (stage[(cb + 2 * j) * 8 + w] >> bit) & 1u;
                unsigned b1 = (stage[(cb + 2 * j + 1) * 8 + w] >> bit) & 1u;
                h[j] = (b0 ? 0x3C00u : 0u) | (b1 ? 0x3C000000u : 0u);
            }
            *(uint4*)(brow + c8 * 16) = make_uint4(h[0], h[1], h[2], h[3]);
        }
    }
    asm volatile("cp.async.wait_group 0;" ::: "memory");
    __syncthreads();

    // Mainloop: warp grid 2(m) x 4(n); warp tile 64m x 32n; K = 128 (8 steps)
    const int warpM = wid >> 2, warpN = wid & 3;
    float acc[4][4][4];
#pragma unroll
    for (int mi = 0; mi < 4; mi++)
#pragma unroll
        for (int ni = 0; ni < 4; ni++)
#pragma unroll
            for (int e = 0; e < 4; e++) acc[mi][ni][e] = 0.f;

    const uint32_t aBase = sb + OFF_A;
    const uint32_t bBase = sb + OFF_B;
    const int lrow = lane & 15, lcol = (lane >> 4) * 16;

#pragma unroll
    for (int k0 = 0; k0 < 8; k0++) {
        uint32_t a[4][4], b[4][2];
#pragma unroll
        for (int mi = 0; mi < 4; mi++) {
            uint32_t addr = aBase + (warpM * 64 + mi * 16 + lrow) * PITCH
                          + k0 * 32 + lcol;
            ldsm4(addr, a[mi][0], a[mi][1], a[mi][2], a[mi][3]);
        }
#pragma unroll
        for (int nb = 0; nb < 2; nb++) {
            uint32_t addr = bBase + (warpN * 32 + nb * 16 + lrow) * PITCH
                          + k0 * 32 + lcol;
            uint32_t r0, r1, r2, r3;
            ldsm4(addr, r0, r1, r2, r3);
            b[nb * 2 + 0][0] = r0; b[nb * 2 + 0][1] = r2;
            b[nb * 2 + 1][0] = r1; b[nb * 2 + 1][1] = r3;
        }
#pragma unroll
        for (int mi = 0; mi < 4; mi++)
#pragma unroll
            for (int ni = 0; ni < 4; ni++)
                mma_f16(acc[mi][ni], a[mi], b[ni]);
    }

    // Epilogue: masked adds (pos & neg) using local masks
    float accp = 0.f, accn = 0.f;
    const int rl = lane >> 2, cl = (lane & 3) << 1;
#pragma unroll
    for (int mi = 0; mi < 4; mi++) {
        int r0 = warpM * 64 + mi * 16 + rl;
        int r1 = r0 + 8;
#pragma unroll
        for (int ni = 0; ni < 4; ni++) {
            int nl = warpN * 32 + ni * 8 + cl;     // 0..127
            int wi = nl >> 5, sh = nl & 31;
            unsigned p0 = maskP[r0 * 4 + wi] >> sh;
            unsigned p1 = maskP[r1 * 4 + wi] >> sh;
            unsigned n0 = maskN[r0 * 4 + wi] >> sh;
            unsigned n1 = maskN[r1 * 4 + wi] >> sh;
            float* c = acc[mi][ni];
            accp += ((p0 & 1u) ? c[0] : 0.f) + ((p0 & 2u) ? c[1] : 0.f)
                  + ((p1 & 1u) ? c[2] : 0.f) + ((p1 & 2u) ? c[3] : 0.f);
            accn += ((n0 & 1u) ? c[0] : 0.f) + ((n0 & 2u) ? c[1] : 0.f)
                  + ((n1 & 1u) ? c[2] : 0.f) + ((n1 & 2u) ? c[3] : 0.f);
        }
    }

#pragma unroll
    for (int off = 16; off > 0; off >>= 1) {
        accp += __shfl_down_sync(0xFFFFFFFFu, accp, off);
        accn += __shfl_down_sync(0xFFFFFFFFu, accn, off);
    }
    if (lane == 0) { red[wid] = accp; red[8 + wid] = accn; }
    __syncthreads();
    if (tid == 0) {
        float sp = 0.f, sn = 0.f;
#pragma unroll
        for (int w = 0; w < 8; w++) { sp += red[w]; sn += red[8 + w]; }
        int slot = oh * 4 + nh * 2 + kh;
        g_ppos[(tq * B_ + bs)   * 8 + slot] = sp;
        g_pneg[(tq * B_ + bneg) * 8 + slot] = sn;
    }
}

// ---------------------------------------------------------------------------
// 3) Finalize
// ---------------------------------------------------------------------------
__global__ void finalize_kernel(float* __restrict__ out) {
    __shared__ float s_neg[TQ][B_];
    __shared__ float s_lsp[NPAIR];
    __shared__ float s_lsn[TQ];
    int tid = threadIdx.x;
    int tq = tid >> 5, b = tid & 31;

    float sp = 0.f, sn = 0.f;
#pragma unroll
    for (int s = 0; s < 8; s++) {
        sp += g_ppos[tid * 8 + s];
        sn += g_pneg[tid * 8 + s];
    }
    float score_pos = expf(sp * (1.0f / (float)CHW)) + 1e-4f;
    float score_neg = expf(sn * (1.0f / (float)CHW)) + 1e-4f;
    float lsp = logf(score_pos);
    s_neg[tq][b] = score_neg;
    s_lsp[tid]   = lsp;
    out[OUT_LSP + tid] = lsp;
    __syncthreads();
    if (b == 0) {
        float s = 0.0f;
#pragma unroll
        for (int bb = 0; bb < B_; bb++) s += s_neg[tq][bb];
        float lsn = logf(s);
        s_lsn[tq] = lsn;
        out[OUT_LSN + tq] = lsn;
    }
    __syncthreads();
    if (tid == 0) {
        float a = 0.0f;
        for (int i = 0; i < NPAIR; i++) a += (-s_lsp[i] + s_lsn[i >> 5]);
        out[OUT_LOSS] = a * (1.0f / (float)NPAIR);
    }
}

// ---------------------------------------------------------------------------
extern "C" void kernel_launch(void* const* d_in, const int* in_sizes, int n_in,
                              void* d_out, int out_size) {
    const float* spk  = (const float*)d_in[0];
    const float* Wg   = (const float*)d_in[2];
    const int*   ridx = (const int*)d_in[3];
    float* out = (float*)d_out;

    static int configured = 0;
    if (!configured) {
        cudaFuncSetAttribute(mma_kernel, cudaFuncAttributeMaxDynamicSharedMemorySize,
                             SMEM_TOTAL);
        configured = 1;
    }

    scan_kernel<<<BCHW / 4 / 256, 256>>>((const float4*)spk, (float4*)out,
                                         (const float4*)Wg);
    mma_kernel<<<NPAIR * 8, 256, SMEM_TOTAL>>>(ridx);   // pair x oh x nh x kh
    finalize_kernel<<<1, NPAIR>>>(out);
}